// round 9
// baseline (speedup 1.0000x reference)
#include <cuda_runtime.h>
#include <stdint.h>

// ---------------------------------------------------------------------------
// Soft-sphere multi-species pair potential: energy, per-atom energies, forces,
// virial stress. Output: [energy(1) | energies(N) | forces(3N) | stress(9)]
// ---------------------------------------------------------------------------

#define MAX_ATOMS 100352   // N_ATOMS = 100000, padded
#define NS_MAX    16

__device__ float4  g_acc[MAX_ATOMS];    // fx, fy, fz, 0.5*sum(e_pair) per atom
__device__ float4  g_pos4[MAX_ATOMS];   // x, y, z, species(int bits)
__device__ double  g_scal[7];           // energy, sxx, syy, szz, sxy, sxz, syz
__device__ int     g_map64;             // 1 if mapping stored as int64
__device__ int     g_spec64;            // 1 if species stored as int64

// Vector global reduction: one 16B red op on sm_90+.
__device__ __forceinline__ void red_add4(float4* addr, float a, float b,
                                         float c, float d) {
#if defined(__CUDA_ARCH__) && (__CUDA_ARCH__ >= 900)
    asm volatile("red.global.add.v4.f32 [%0], {%1, %2, %3, %4};"
                 :: "l"(addr), "f"(a), "f"(b), "f"(c), "f"(d)
                 : "memory");
#else
    atomicAdd(&addr->x, a);
    atomicAdd(&addr->y, b);
    atomicAdd(&addr->z, c);
    atomicAdd(&addr->w, d);
#endif
}

// ---------------------------------------------------------------------------
// Detect int64 vs int32 storage (one warp; all 128 loads in flight).
// ---------------------------------------------------------------------------
__global__ void detect_kernel(const int* __restrict__ mapw,
                              const int* __restrict__ specw) {
    int t = threadIdx.x;
    int m = mapw[2 * t + 1]  | mapw[2 * (t + 32) + 1];
    int s = specw[2 * t + 1] | specw[2 * (t + 32) + 1];
    unsigned bm = __ballot_sync(0xffffffffu, m != 0);
    unsigned bs = __ballot_sync(0xffffffffu, s != 0);
    if (t == 0) {
        g_map64  = (bm == 0u);
        g_spec64 = (bs == 0u);
    }
}

__global__ void init_zero_kernel(int n) {
    int t = blockIdx.x * blockDim.x + threadIdx.x;
    if (t < n) g_acc[t] = make_float4(0.f, 0.f, 0.f, 0.f);
    if (t < 7) g_scal[t] = 0.0;
}

__global__ void init_pos_kernel(const float* __restrict__ pos,
                                const void*  __restrict__ spec,
                                int n) {
    int t = blockIdx.x * blockDim.x + threadIdx.x;
    if (t < n) {
        int sp;
        if (g_spec64) sp = (int)((const long long*)spec)[t];
        else          sp = ((const int*)spec)[t];
        g_pos4[t] = make_float4(pos[3 * t], pos[3 * t + 1], pos[3 * t + 2],
                                __int_as_float(sp));
    }
}

// ---------------------------------------------------------------------------
// Shared pair-parameter tables + per-thread accumulator state.
// ---------------------------------------------------------------------------
struct PairTables {
    float sg2[NS_MAX * NS_MAX];
    float isg[NS_MAX * NS_MAX];
    float ea [NS_MAX * NS_MAX];
    float es [NS_MAX * NS_MAX];
    float am1[NS_MAX * NS_MAX];
    float cell[9];
    float red[7][8];
};

struct Accum {
    float en, sxx, syy, szz, sxy, sxz, syz;
};

__device__ __forceinline__ void load_tables(PairTables& T,
                                            const float* sigm, const float* epsm,
                                            const float* alpm, const float* cell,
                                            int ns) {
    int tid = threadIdx.x;
    for (int q = tid; q < ns * ns; q += blockDim.x) {
        float sg = sigm[q], ep = epsm[q], al = alpm[q];
        T.sg2[q] = sg * sg;
        T.isg[q] = 1.0f / sg;
        T.ea [q] = 0.5f * ep / al;
        T.es [q] = ep / sg;
        T.am1[q] = al - 1.0f;
    }
    if (tid < 9) T.cell[tid] = cell[tid];
    __syncthreads();
}

// One pair: displacement -> gated energy/force -> accumulate + scatter.
__device__ __forceinline__ void pair_compute(const PairTables& T, Accum& A,
                                             float4 pi, float4 pj,
                                             float s0, float s1, float s2,
                                             int i, int j, int ns) {
    float dx = pj.x - pi.x + s0 * T.cell[0] + s1 * T.cell[3] + s2 * T.cell[6];
    float dy = pj.y - pi.y + s0 * T.cell[1] + s1 * T.cell[4] + s2 * T.cell[7];
    float dz = pj.z - pi.z + s0 * T.cell[2] + s1 * T.cell[5] + s2 * T.cell[8];
    float r2 = dx * dx + dy * dy + dz * dz;
    int q = __float_as_int(pi.w) * ns + __float_as_int(pj.w);
    if (r2 < T.sg2[q]) {
        float rinv = rsqrtf(r2);
        float r    = r2 * rinv;
        float base = 1.0f - r * T.isg[q];
        float pm1  = __powf(base, T.am1[q]);
        float he   = T.ea[q] * pm1 * base;     // 0.5 * e_pair
        float c    = T.es[q] * pm1 * rinv;     // f_pair / r
        float fx = c * dx, fy = c * dy, fz = c * dz;
        A.en  += he;
        A.sxx += fx * dx; A.syy += fy * dy; A.szz += fz * dz;
        A.sxy += fx * dy; A.sxz += fx * dz; A.syz += fy * dz;
        red_add4(g_acc + i,  fx,  fy,  fz, he);
        red_add4(g_acc + j, -fx, -fy, -fz, he);
    }
}

__device__ __forceinline__ void reduce_scalars(PairTables& T, const Accum& A) {
    float v[7] = {A.en, A.sxx, A.syy, A.szz, A.sxy, A.sxz, A.syz};
    int tid = threadIdx.x;
    int lane = tid & 31, warp = tid >> 5;
    #pragma unroll
    for (int q = 0; q < 7; q++) {
        float x = v[q];
        #pragma unroll
        for (int o = 16; o > 0; o >>= 1) x += __shfl_down_sync(0xffffffffu, x, o);
        if (lane == 0) T.red[q][warp] = x;
    }
    __syncthreads();
    if (tid < 7) {
        float x = 0.f;
        int nw = (blockDim.x + 31) >> 5;
        for (int w = 0; w < nw; w++) x += T.red[tid][w];
        atomicAdd(&g_scal[tid], (double)x);
    }
}

// ---------------------------------------------------------------------------
// Quad pair kernel: 4 pairs per thread per iteration; all mapping/shift loads
// and all 8 position gathers are independent and issued before any compute.
// Requires nPairs % 4 == 0.
// ---------------------------------------------------------------------------
__global__ __launch_bounds__(256)
void pair_quad_kernel(const void*  __restrict__ map,
                      const float* __restrict__ shifts,
                      const float* __restrict__ cell,
                      const float* __restrict__ sigm,
                      const float* __restrict__ epsm,
                      const float* __restrict__ alpm,
                      int nPairs, int ns) {
    __shared__ PairTables T;
    load_tables(T, sigm, epsm, alpm, cell, ns);

    Accum A = {0.f, 0.f, 0.f, 0.f, 0.f, 0.f, 0.f};

    const int m64 = g_map64;
    const int nQuad = nPairs >> 2;
    const int stride = gridDim.x * blockDim.x;

    for (int t = blockIdx.x * blockDim.x + threadIdx.x; t < nQuad; t += stride) {
        int p = t << 2;
        int i0, i1, i2, i3, j0, j1, j2, j3;
        if (m64) {
            const long long* mp = (const long long*)map;
            int4 a0 = *(const int4*)(mp + p);
            int4 a1 = *(const int4*)(mp + p + 2);
            int4 b0 = *(const int4*)(mp + nPairs + p);
            int4 b1 = *(const int4*)(mp + nPairs + p + 2);
            i0 = a0.x; i1 = a0.z; i2 = a1.x; i3 = a1.z;
            j0 = b0.x; j1 = b0.z; j2 = b1.x; j3 = b1.z;
        } else {
            const int* mp = (const int*)map;
            int4 a = *(const int4*)(mp + p);
            int4 b = *(const int4*)(mp + nPairs + p);
            i0 = a.x; i1 = a.y; i2 = a.z; i3 = a.w;
            j0 = b.x; j1 = b.y; j2 = b.z; j3 = b.w;
        }
        float4 sA = *(const float4*)(shifts + 3 * p);
        float4 sB = *(const float4*)(shifts + 3 * p + 4);
        float4 sC = *(const float4*)(shifts + 3 * p + 8);

        float4 pi0 = g_pos4[i0], pj0 = g_pos4[j0];
        float4 pi1 = g_pos4[i1], pj1 = g_pos4[j1];
        float4 pi2 = g_pos4[i2], pj2 = g_pos4[j2];
        float4 pi3 = g_pos4[i3], pj3 = g_pos4[j3];

        pair_compute(T, A, pi0, pj0, sA.x, sA.y, sA.z, i0, j0, ns);
        pair_compute(T, A, pi1, pj1, sA.w, sB.x, sB.y, i1, j1, ns);
        pair_compute(T, A, pi2, pj2, sB.z, sB.w, sC.x, i2, j2, ns);
        pair_compute(T, A, pi3, pj3, sC.y, sC.z, sC.w, i3, j3, ns);
    }

    reduce_scalars(T, A);
}

// ---------------------------------------------------------------------------
// Fallback scalar kernel (any nPairs).
// ---------------------------------------------------------------------------
__global__ __launch_bounds__(256)
void pair_scalar_kernel(const void*  __restrict__ map,
                        const float* __restrict__ shifts,
                        const float* __restrict__ cell,
                        const float* __restrict__ sigm,
                        const float* __restrict__ epsm,
                        const float* __restrict__ alpm,
                        int nPairs, int ns) {
    __shared__ PairTables T;
    load_tables(T, sigm, epsm, alpm, cell, ns);

    Accum A = {0.f, 0.f, 0.f, 0.f, 0.f, 0.f, 0.f};
    const int m64 = g_map64;
    const long long* map64p = (const long long*)map;
    const int*       map32p = (const int*)map;

    int stride = gridDim.x * blockDim.x;
    for (int p = blockIdx.x * blockDim.x + threadIdx.x; p < nPairs; p += stride) {
        int i, j;
        if (m64) { i = (int)map64p[p]; j = (int)map64p[nPairs + p]; }
        else     { i = map32p[p];      j = map32p[nPairs + p]; }
        float4 pi = g_pos4[i];
        float4 pj = g_pos4[j];
        pair_compute(T, A, pi, pj,
                     shifts[3 * p], shifts[3 * p + 1], shifts[3 * p + 2],
                     i, j, ns);
    }

    reduce_scalars(T, A);
}

// ---------------------------------------------------------------------------
// Finalize: coalesced load of g_acc, smem transpose, coalesced stores.
// ---------------------------------------------------------------------------
__global__ __launch_bounds__(256)
void finalize_kernel(float* __restrict__ out,
                     const float* __restrict__ cell, int n) {
    __shared__ float sf[768];
    int t = threadIdx.x;
    int base = blockIdx.x * 256;
    int rem = n - base;
    if (rem > 256) rem = 256;

    if (t < rem) {
        float4 a = g_acc[base + t];
        out[1 + base + t] = a.w;
        sf[3 * t + 0] = a.x;
        sf[3 * t + 1] = a.y;
        sf[3 * t + 2] = a.z;
    }
    __syncthreads();
    int fb = 1 + n + 3 * base;
    int m3 = 3 * rem;
    #pragma unroll
    for (int k = 0; k < 3; k++) {
        int idx = t + k * 256;
        if (idx < m3) out[fb + idx] = sf[idx];
    }

    if (blockIdx.x == 0 && t == 0) {
        out[0] = (float)g_scal[0];
        float a00 = cell[0], a01 = cell[1], a02 = cell[2];
        float a10 = cell[3], a11 = cell[4], a12 = cell[5];
        float a20 = cell[6], a21 = cell[7], a22 = cell[8];
        float det = a00 * (a11 * a22 - a12 * a21)
                  - a01 * (a10 * a22 - a12 * a20)
                  + a02 * (a10 * a21 - a11 * a20);
        double inv_vol = 1.0 / (double)fabsf(det);
        double s[6];
        for (int q = 0; q < 6; q++) s[q] = g_scal[1 + q];
        const int idx[3][3] = {{0, 3, 4}, {3, 1, 5}, {4, 5, 2}};
        for (int a = 0; a < 3; a++)
            for (int b = 0; b < 3; b++)
                out[1 + 4 * n + 3 * a + b] = (float)(-s[idx[a][b]] * inv_vol);
    }
}

// ---------------------------------------------------------------------------
extern "C" void kernel_launch(void* const* d_in, const int* in_sizes, int n_in,
                              void* d_out, int out_size) {
    // metadata order: positions, cell, sigma_matrix, epsilon_matrix,
    //                 alpha_matrix, shifts, mapping, species
    const float* pos    = (const float*)d_in[0];
    const float* cell   = (const float*)d_in[1];
    const float* sigm   = (const float*)d_in[2];
    const float* epsm   = (const float*)d_in[3];
    const float* alpm   = (const float*)d_in[4];
    const float* shifts = (const float*)d_in[5];
    const void*  map    = d_in[6];
    const void*  spec   = d_in[7];

    int n  = in_sizes[0] / 3;   // atoms
    int P  = in_sizes[5] / 3;   // pairs (shifts is [P,3] f32, dtype-unambiguous)
    int m2 = in_sizes[2];
    int ns = 1;
    while (ns * ns < m2) ns++;
    if (ns > NS_MAX) ns = NS_MAX;

    detect_kernel<<<1, 32>>>((const int*)map, (const int*)spec);
    init_zero_kernel<<<(n + 255) / 256, 256>>>(n);
    init_pos_kernel<<<(n + 255) / 256, 256>>>(pos, spec, n);
    if ((P & 3) == 0) {
        int nQuad = P >> 2;
        int blocks = (nQuad + 255) / 256;
        if (blocks > 3200) blocks = 3200;
        pair_quad_kernel<<<blocks, 256>>>(map, shifts, cell,
                                          sigm, epsm, alpm, P, ns);
    } else {
        pair_scalar_kernel<<<2048, 256>>>(map, shifts, cell,
                                          sigm, epsm, alpm, P, ns);
    }
    finalize_kernel<<<(n + 255) / 256, 256>>>((float*)d_out, cell, n);
}